// round 4
// baseline (speedup 1.0000x reference)
#include <cuda_runtime.h>

// Shapes (fixed by the problem)
#define BB 16
#define NNODE 512
#define MNB 16
#define HH 8
#define DD 128
#define BN 8192     // BB*NNODE
#define HD 1024     // HH*DD
#define FFD 256

// Scratch (device globals; no runtime allocation)
__device__ float g_Wh[(size_t)BN * HD];     // [node][h*128+e]
__device__ float g_ssrc[(size_t)BN * HH];
__device__ float g_sdst[(size_t)BN * HH];
__device__ float g_agg[(size_t)BN * HD];
__device__ float g_t[(size_t)BN * DD];
__device__ float g_u[(size_t)BN * FFD];

__device__ __forceinline__ float warp_sum(float v) {
#pragma unroll
    for (int o = 16; o > 0; o >>= 1) v += __shfl_xor_sync(0xffffffffu, v, o);
    return v;
}

// ---------------------------------------------------------------------------
// K1: Wh[node,h,:] = h[node,:] @ W[h]; fused s_src/s_dst = Wh . a_src/a_dst.
// grid (256 node-tiles of 32, 8 heads), 256 threads, 4x4 register tile.
// ---------------------------------------------------------------------------
__global__ void __launch_bounds__(256) k1_wh(
    const float* __restrict__ h, const float* __restrict__ W,
    const float* __restrict__ a_src, const float* __restrict__ a_dst)
{
    __shared__ float As[128 * 40];   // As[d*40 + r], rows of 4 floats 16B-aligned
    __shared__ float Ws[32 * 128];   // Ws[k*128 + e]

    const int tx = threadIdx.x;
    const int lane = tx & 31;
    const int trow = tx >> 5;
    const int n0 = blockIdx.x * 32;
    const int head = blockIdx.y;

    // A tile transposed: As[d][r] = h[(n0+r)*128 + d]  (coalesced global reads)
    for (int idx = tx; idx < 32 * 128; idx += 256) {
        int r = idx >> 7, d = idx & 127;
        As[d * 40 + r] = h[(size_t)(n0 + r) * 128 + d];
    }

    float acc[4][4];
#pragma unroll
    for (int i = 0; i < 4; i++)
#pragma unroll
        for (int j = 0; j < 4; j++) acc[i][j] = 0.f;

    const float* Whead = W + (size_t)head * 128 * 128;

    for (int k0 = 0; k0 < 128; k0 += 32) {
        __syncthreads();
        for (int idx = tx; idx < 32 * 128; idx += 256) {
            Ws[idx] = Whead[(size_t)(k0 << 7) + idx];   // (k0+k)*128 + e
        }
        __syncthreads();
#pragma unroll
        for (int k = 0; k < 32; ++k) {
            const float4 w = *(const float4*)(Ws + k * 128 + lane * 4);
            const float4 a = *(const float4*)(As + (k0 + k) * 40 + trow * 4);
            const float av[4] = {a.x, a.y, a.z, a.w};
            const float wv[4] = {w.x, w.y, w.z, w.w};
#pragma unroll
            for (int i = 0; i < 4; i++)
#pragma unroll
                for (int j = 0; j < 4; j++)
                    acc[i][j] = fmaf(av[i], wv[j], acc[i][j]);
        }
    }

    const float4 asv = *(const float4*)(a_src + head * 128 + lane * 4);
    const float4 adv = *(const float4*)(a_dst + head * 128 + lane * 4);

#pragma unroll
    for (int i = 0; i < 4; i++) {
        const int row = n0 + trow * 4 + i;
        float4 c = make_float4(acc[i][0], acc[i][1], acc[i][2], acc[i][3]);
        *(float4*)(g_Wh + (size_t)row * HD + head * 128 + lane * 4) = c;
        float ps = c.x * asv.x + c.y * asv.y + c.z * asv.z + c.w * asv.w;
        float pd = c.x * adv.x + c.y * adv.y + c.z * adv.z + c.w * adv.w;
        ps = warp_sum(ps);
        pd = warp_sum(pd);
        if (lane == 0) {
            g_ssrc[(size_t)row * HH + head] = ps;
            g_sdst[(size_t)row * HH + head] = pd;
        }
    }
}

// ---------------------------------------------------------------------------
// K2: attention (leaky_relu + mask + softmax over M) and neighbor aggregation.
// One block per node; 256 threads; float4 gather from L2-resident g_Wh.
// ---------------------------------------------------------------------------
__global__ void __launch_bounds__(256) k2_attn(
    const int* __restrict__ adj, const int* __restrict__ nlist)
{
    const int node = blockIdx.x;
    const int b = node >> 9;
    const int tx = threadIdx.x;

    __shared__ int   nls[MNB];
    __shared__ int   adjs[MNB];
    __shared__ float es[MNB][HH];
    __shared__ float attn_s[MNB][HH];

    if (tx < MNB) {
        nls[tx]  = nlist[(size_t)node * MNB + tx];
        adjs[tx] = adj[(size_t)node * MNB + tx];
    }
    __syncthreads();

    if (tx < MNB * HH) {
        const int m = tx >> 3, hh = tx & 7;
        float v = g_ssrc[(size_t)node * HH + hh]
                + g_sdst[(size_t)((b << 9) + nls[m]) * HH + hh];
        v = v > 0.f ? v : 0.2f * v;            // leaky_relu
        if (adjs[m] <= 0) v = -1e9f;           // mask
        es[m][hh] = v;
    }
    __syncthreads();

    if (tx < HH) {
        float mx = -3.4e38f;
#pragma unroll
        for (int m = 0; m < MNB; m++) mx = fmaxf(mx, es[m][tx]);
        float ex[MNB], s = 0.f;
#pragma unroll
        for (int m = 0; m < MNB; m++) { ex[m] = expf(es[m][tx] - mx); s += ex[m]; }
        const float inv = 1.f / s;
#pragma unroll
        for (int m = 0; m < MNB; m++) attn_s[m][tx] = ex[m] * inv;
    }
    __syncthreads();

    // Each thread owns 4 consecutive output elements (one head slice per 32 threads)
    const int hh = tx >> 5;
    const float4* whb = (const float4*)g_Wh + (size_t)(b << 9) * 256;
    float4 acc = make_float4(0.f, 0.f, 0.f, 0.f);
#pragma unroll
    for (int m = 0; m < MNB; m++) {
        const float wgt = attn_s[m][hh];
        const float4 v = whb[(size_t)nls[m] * 256 + tx];
        acc.x = fmaf(wgt, v.x, acc.x);
        acc.y = fmaf(wgt, v.y, acc.y);
        acc.z = fmaf(wgt, v.z, acc.z);
        acc.w = fmaf(wgt, v.w, acc.w);
    }
    ((float4*)g_agg)[(size_t)node * 256 + tx] = acc;
}

// ---------------------------------------------------------------------------
// K3: y = agg @ Wo  (+ h residual), LayerNorm1 -> g_t.
// grid 256 (32 rows each), 256 threads, 4x4 tile, K=1024 chunked by 32.
// ---------------------------------------------------------------------------
__global__ void __launch_bounds__(256) k3_proj_ln1(
    const float* __restrict__ h, const float* __restrict__ Wo,
    const float* __restrict__ g1, const float* __restrict__ b1)
{
    __shared__ float As[32 * 40];
    __shared__ float Ws[32 * 128];

    const int tx = threadIdx.x;
    const int lane = tx & 31;
    const int trow = tx >> 5;
    const int n0 = blockIdx.x * 32;

    float acc[4][4];
#pragma unroll
    for (int i = 0; i < 4; i++)
#pragma unroll
        for (int j = 0; j < 4; j++) acc[i][j] = 0.f;

    for (int k0 = 0; k0 < HD; k0 += 32) {
        for (int idx = tx; idx < 32 * 32; idx += 256) {
            int r = idx >> 5, k = idx & 31;
            As[k * 40 + r] = g_agg[(size_t)(n0 + r) * HD + k0 + k];
        }
        for (int idx = tx; idx < 32 * 128; idx += 256) {
            int k = idx >> 7, e = idx & 127;
            Ws[idx] = Wo[(size_t)(k0 + k) * 128 + e];
        }
        __syncthreads();
#pragma unroll
        for (int k = 0; k < 32; ++k) {
            const float4 w = *(const float4*)(Ws + k * 128 + lane * 4);
            const float4 a = *(const float4*)(As + k * 40 + trow * 4);
            const float av[4] = {a.x, a.y, a.z, a.w};
            const float wv[4] = {w.x, w.y, w.z, w.w};
#pragma unroll
            for (int i = 0; i < 4; i++)
#pragma unroll
                for (int j = 0; j < 4; j++)
                    acc[i][j] = fmaf(av[i], wv[j], acc[i][j]);
        }
        __syncthreads();
    }

    const float4 gg = *(const float4*)(g1 + lane * 4);
    const float4 bb = *(const float4*)(b1 + lane * 4);

#pragma unroll
    for (int i = 0; i < 4; i++) {
        const int row = n0 + trow * 4 + i;
        const float4 hv = *(const float4*)(h + (size_t)row * 128 + lane * 4);
        float x0 = acc[i][0] + hv.x, x1 = acc[i][1] + hv.y;
        float x2 = acc[i][2] + hv.z, x3 = acc[i][3] + hv.w;
        const float mu = warp_sum(x0 + x1 + x2 + x3) * (1.f / 128.f);
        x0 -= mu; x1 -= mu; x2 -= mu; x3 -= mu;
        const float var = warp_sum(x0 * x0 + x1 * x1 + x2 * x2 + x3 * x3) * (1.f / 128.f);
        const float rs = rsqrtf(var + 1e-5f);
        float4 y;
        y.x = x0 * rs * gg.x + bb.x;
        y.y = x1 * rs * gg.y + bb.y;
        y.z = x2 * rs * gg.z + bb.z;
        y.w = x3 * rs * gg.w + bb.w;
        *(float4*)(g_t + (size_t)row * 128 + lane * 4) = y;
    }
}

// ---------------------------------------------------------------------------
// K4a: u = relu(t @ ff_w1 + b1) -> g_u.  [8192,128]@[128,256]
// grid 256, 256 threads, 4x8 tile, K=128 in smem, W1 chunked BK=16.
// ---------------------------------------------------------------------------
__global__ void __launch_bounds__(256) k4a_ff1(
    const float* __restrict__ w1, const float* __restrict__ bb1)
{
    __shared__ float Ts[128 * 40];
    __shared__ float W1s[16 * 256];

    const int tx = threadIdx.x;
    const int lane = tx & 31;
    const int trow = tx >> 5;
    const int n0 = blockIdx.x * 32;

    for (int idx = tx; idx < 32 * 128; idx += 256) {
        int r = idx >> 7, k = idx & 127;
        Ts[k * 40 + r] = g_t[(size_t)(n0 + r) * 128 + k];
    }

    float acc[4][8];
#pragma unroll
    for (int i = 0; i < 4; i++)
#pragma unroll
        for (int j = 0; j < 8; j++) acc[i][j] = 0.f;

    for (int k0 = 0; k0 < 128; k0 += 16) {
        __syncthreads();
        for (int idx = tx; idx < 16 * 256; idx += 256) {
            W1s[idx] = w1[(size_t)(k0 << 8) + idx];   // (k0+k)*256 + c
        }
        __syncthreads();
#pragma unroll
        for (int k = 0; k < 16; ++k) {
            const float4 a = *(const float4*)(Ts + (k0 + k) * 40 + trow * 4);
            const float4 w0 = *(const float4*)(W1s + k * 256 + lane * 8);
            const float4 w1v = *(const float4*)(W1s + k * 256 + lane * 8 + 4);
            const float av[4] = {a.x, a.y, a.z, a.w};
            const float wv[8] = {w0.x, w0.y, w0.z, w0.w, w1v.x, w1v.y, w1v.z, w1v.w};
#pragma unroll
            for (int i = 0; i < 4; i++)
#pragma unroll
                for (int j = 0; j < 8; j++)
                    acc[i][j] = fmaf(av[i], wv[j], acc[i][j]);
        }
    }

    const float4 bA = *(const float4*)(bb1 + lane * 8);
    const float4 bBv = *(const float4*)(bb1 + lane * 8 + 4);
    const float bv[8] = {bA.x, bA.y, bA.z, bA.w, bBv.x, bBv.y, bBv.z, bBv.w};

#pragma unroll
    for (int i = 0; i < 4; i++) {
        const int row = n0 + trow * 4 + i;
        float4 u0, u1;
        u0.x = fmaxf(acc[i][0] + bv[0], 0.f);
        u0.y = fmaxf(acc[i][1] + bv[1], 0.f);
        u0.z = fmaxf(acc[i][2] + bv[2], 0.f);
        u0.w = fmaxf(acc[i][3] + bv[3], 0.f);
        u1.x = fmaxf(acc[i][4] + bv[4], 0.f);
        u1.y = fmaxf(acc[i][5] + bv[5], 0.f);
        u1.z = fmaxf(acc[i][6] + bv[6], 0.f);
        u1.w = fmaxf(acc[i][7] + bv[7], 0.f);
        ((float4*)g_u)[(size_t)row * 64 + lane * 2]     = u0;
        ((float4*)g_u)[(size_t)row * 64 + lane * 2 + 1] = u1;
    }
}

// ---------------------------------------------------------------------------
// K4b: y = u @ ff_w2 + b2 + t, LayerNorm2 -> out.  [8192,256]@[256,128]
// ---------------------------------------------------------------------------
__global__ void __launch_bounds__(256) k4b_ff2_ln2(
    const float* __restrict__ w2, const float* __restrict__ bb2,
    const float* __restrict__ g2, const float* __restrict__ be2,
    float* __restrict__ out)
{
    __shared__ float As[32 * 40];
    __shared__ float Ws[32 * 128];

    const int tx = threadIdx.x;
    const int lane = tx & 31;
    const int trow = tx >> 5;
    const int n0 = blockIdx.x * 32;

    float acc[4][4];
#pragma unroll
    for (int i = 0; i < 4; i++)
#pragma unroll
        for (int j = 0; j < 4; j++) acc[i][j] = 0.f;

    for (int k0 = 0; k0 < FFD; k0 += 32) {
        for (int idx = tx; idx < 32 * 32; idx += 256) {
            int r = idx >> 5, k = idx & 31;
            As[k * 40 + r] = g_u[(size_t)(n0 + r) * FFD + k0 + k];
        }
        for (int idx = tx; idx < 32 * 128; idx += 256) {
            int k = idx >> 7, e = idx & 127;
            Ws[idx] = w2[(size_t)(k0 + k) * 128 + e];
        }
        __syncthreads();
#pragma unroll
        for (int k = 0; k < 32; ++k) {
            const float4 w = *(const float4*)(Ws + k * 128 + lane * 4);
            const float4 a = *(const float4*)(As + k * 40 + trow * 4);
            const float av[4] = {a.x, a.y, a.z, a.w};
            const float wv[4] = {w.x, w.y, w.z, w.w};
#pragma unroll
            for (int i = 0; i < 4; i++)
#pragma unroll
                for (int j = 0; j < 4; j++)
                    acc[i][j] = fmaf(av[i], wv[j], acc[i][j]);
        }
        __syncthreads();
    }

    const float4 b2v = *(const float4*)(bb2 + lane * 4);
    const float4 gg = *(const float4*)(g2 + lane * 4);
    const float4 bb = *(const float4*)(be2 + lane * 4);

#pragma unroll
    for (int i = 0; i < 4; i++) {
        const int row = n0 + trow * 4 + i;
        const float4 tv = *(const float4*)(g_t + (size_t)row * 128 + lane * 4);
        float x0 = acc[i][0] + b2v.x + tv.x;
        float x1 = acc[i][1] + b2v.y + tv.y;
        float x2 = acc[i][2] + b2v.z + tv.z;
        float x3 = acc[i][3] + b2v.w + tv.w;
        const float mu = warp_sum(x0 + x1 + x2 + x3) * (1.f / 128.f);
        x0 -= mu; x1 -= mu; x2 -= mu; x3 -= mu;
        const float var = warp_sum(x0 * x0 + x1 * x1 + x2 * x2 + x3 * x3) * (1.f / 128.f);
        const float rs = rsqrtf(var + 1e-5f);
        float4 y;
        y.x = x0 * rs * gg.x + bb.x;
        y.y = x1 * rs * gg.y + bb.y;
        y.z = x2 * rs * gg.z + bb.z;
        y.w = x3 * rs * gg.w + bb.w;
        *(float4*)(out + (size_t)row * 128 + lane * 4) = y;
    }
}

// ---------------------------------------------------------------------------
extern "C" void kernel_launch(void* const* d_in, const int* in_sizes, int n_in,
                              void* d_out, int out_size)
{
    const float* h     = (const float*)d_in[0];
    const int*   adj   = (const int*)d_in[1];
    const int*   nlist = (const int*)d_in[2];
    const float* W     = (const float*)d_in[3];
    const float* a_src = (const float*)d_in[4];
    const float* a_dst = (const float*)d_in[5];
    const float* Wo    = (const float*)d_in[6];
    const float* ln1g  = (const float*)d_in[7];
    const float* ln1b  = (const float*)d_in[8];
    const float* w1    = (const float*)d_in[9];
    const float* b1    = (const float*)d_in[10];
    const float* w2    = (const float*)d_in[11];
    const float* b2    = (const float*)d_in[12];
    const float* ln2g  = (const float*)d_in[13];
    const float* ln2b  = (const float*)d_in[14];
    float* out = (float*)d_out;

    k1_wh<<<dim3(BN / 32, HH), 256>>>(h, W, a_src, a_dst);
    k2_attn<<<BN, 256>>>(adj, nlist);
    k3_proj_ln1<<<BN / 32, 256>>>(h, Wo, ln1g, ln1b);
    k4a_ff1<<<BN / 32, 256>>>(w1, b1);
    k4b_ff2_ln2<<<BN / 32, 256>>>(w2, b2, ln2g, ln2b, out);
}

// round 6
// speedup vs baseline: 2.8842x; 2.8842x over previous
#include <cuda_runtime.h>
#include <cuda_bf16.h>
#include <cstdint>

#define BB 16
#define NNODE 512
#define MNB 16
#define HH 8
#define DD 128
#define BN 8192
#define HD 1024
#define FFD 256

// ---------------- scratch globals (no runtime allocation) ----------------
__device__ float g_Wh[(size_t)BN * HD];
__device__ float g_ssrc[(size_t)BN * HH];
__device__ float g_sdst[(size_t)BN * HH];
__device__ float g_agg[(size_t)BN * HD];
__device__ float g_t[(size_t)BN * DD];
__device__ float g_u[(size_t)BN * FFD];

__device__ __nv_bfloat16 g_Wt_hi[(size_t)HH * DD * DD];  // [h][e][d]
__device__ __nv_bfloat16 g_Wt_lo[(size_t)HH * DD * DD];
__device__ __nv_bfloat16 g_Wot_hi[(size_t)DD * HD];      // [n][k] ldb=1024
__device__ __nv_bfloat16 g_Wot_lo[(size_t)DD * HD];
__device__ __nv_bfloat16 g_w1t_hi[(size_t)FFD * DD];     // [n][k] ldb=128
__device__ __nv_bfloat16 g_w1t_lo[(size_t)FFD * DD];
__device__ __nv_bfloat16 g_w2t_hi[(size_t)DD * FFD];     // [n][k] ldb=256
__device__ __nv_bfloat16 g_w2t_lo[(size_t)DD * FFD];

// ---------------- smem layout ----------------
// bf16 tiles, row pitch 136 elems (272B) -> conflict-free 32-bit fragment loads
#define APITCH 136
#define TILE_BYTES (128 * APITCH * 2)   // 34816
#define OFF_AH 2048
#define OFF_AL (OFF_AH + TILE_BYTES)
#define OFF_BH (OFF_AL + TILE_BYTES)
#define OFF_BL (OFF_BH + TILE_BYTES)
#define GEMM_SMEM (OFF_BL + TILE_BYTES)  // 141312
#define SPITCH 132                       // fp32 staging pitch (16B-aligned rows)

__device__ __forceinline__ uint32_t lds32(const __nv_bfloat16* base, int r, int c) {
    return *(const uint32_t*)((const char*)base + ((size_t)r * APITCH + c) * 2);
}

__device__ __forceinline__ void mma16816(float* d, const uint32_t* a,
                                         uint32_t b0, uint32_t b1) {
    asm volatile(
        "mma.sync.aligned.m16n8k16.row.col.f32.bf16.bf16.f32 "
        "{%0,%1,%2,%3}, {%4,%5,%6,%7}, {%8,%9}, {%0,%1,%2,%3};"
        : "+f"(d[0]), "+f"(d[1]), "+f"(d[2]), "+f"(d[3])
        : "r"(a[0]), "r"(a[1]), "r"(a[2]), "r"(a[3]), "r"(b0), "r"(b1));
}

__device__ __forceinline__ void split4(float4 v, uint2& hi, uint2& lo) {
    __nv_bfloat162 h0 = __floats2bfloat162_rn(v.x, v.y);
    __nv_bfloat162 h1 = __floats2bfloat162_rn(v.z, v.w);
    __nv_bfloat162 l0 = __floats2bfloat162_rn(v.x - __bfloat162float(h0.x),
                                              v.y - __bfloat162float(h0.y));
    __nv_bfloat162 l1 = __floats2bfloat162_rn(v.z - __bfloat162float(h1.x),
                                              v.w - __bfloat162float(h1.y));
    hi = make_uint2(*(uint32_t*)&h0, *(uint32_t*)&h1);
    lo = make_uint2(*(uint32_t*)&l0, *(uint32_t*)&l1);
}

// ---------------- prep: transpose + bf16-split all weights ----------------
__global__ void __launch_bounds__(256) prep_weights(
    const float* __restrict__ W, const float* __restrict__ Wo,
    const float* __restrict__ w1, const float* __restrict__ w2)
{
    int i = blockIdx.x * 256 + threadIdx.x;
    float v; size_t dst; __nv_bfloat16 *ph, *pl;
    if (i < 131072) {                      // W[h][d][e] -> Wt[h][e][d]
        int h = i >> 14, d = (i >> 7) & 127, e = i & 127;
        v = W[i]; dst = (size_t)h * 16384 + (size_t)e * 128 + d;
        ph = g_Wt_hi; pl = g_Wt_lo;
    } else if (i < 262144) {               // Wo[k][n] -> Wot[n][k]
        int j = i - 131072; int k = j >> 7, n = j & 127;
        v = Wo[j]; dst = (size_t)n * 1024 + k;
        ph = g_Wot_hi; pl = g_Wot_lo;
    } else if (i < 294912) {               // w1[k][n] -> w1t[n][k]
        int j = i - 262144; int k = j >> 8, n = j & 255;
        v = w1[j]; dst = (size_t)n * 128 + k;
        ph = g_w1t_hi; pl = g_w1t_lo;
    } else if (i < 327680) {               // w2[k][n] -> w2t[n][k]
        int j = i - 294912; int k = j >> 7, n = j & 127;
        v = w2[j]; dst = (size_t)n * 256 + k;
        ph = g_w2t_hi; pl = g_w2t_lo;
    } else return;
    __nv_bfloat16 hb = __float2bfloat16(v);
    ph[dst] = hb;
    pl[dst] = __float2bfloat16(v - __bfloat162float(hb));
}

// ---------------- generic HMMA GEMM with fused epilogue ----------------
// MODE 0: Wh = h @ W[head], + ssrc/sdst dots     (grid 64 x 8)
// MODE 1: t  = LN1(agg @ Wo + h)                 (grid 64, KP=8)
// MODE 2: u  = relu(t @ w1 + b1)                 (grid 64 x 2)
// MODE 3: out= LN2(u @ w2 + b2 + t)              (grid 64, KP=2)
template <int MODE>
__global__ void __launch_bounds__(256, 1) gemm_mma(
    const float* __restrict__ Aext, const float* __restrict__ p0,
    const float* __restrict__ p1, const float* __restrict__ p2,
    float* __restrict__ outp)
{
    extern __shared__ char sm[];
    const int tid = threadIdx.x;
    const int warp = tid >> 5;
    const int lane = tid & 31;
    const int n0 = blockIdx.x * 128;
    const int by = blockIdx.y;
    const int wm = (warp & 1) * 64;
    const int wn = (warp >> 1) * 32;
    const int rr = lane >> 2;
    const int cc = (lane & 3) * 2;

    constexpr int LDA = (MODE == 0) ? 128 : (MODE == 1) ? 1024 : (MODE == 2) ? 128 : 256;
    constexpr int LDB = (MODE == 0) ? 128 : (MODE == 1) ? 1024 : (MODE == 2) ? 128 : 256;
    constexpr int KP  = (MODE == 1) ? 8 : (MODE == 3) ? 2 : 1;
    constexpr int LDOUT = (MODE == 0) ? 1024 : (MODE == 2) ? 256 : 128;

    const float* A = (MODE == 0) ? Aext : (MODE == 1) ? g_agg : (MODE == 2) ? g_t : g_u;
    const __nv_bfloat16 *Bh, *Bl;
    int coff = 0;
    if (MODE == 0) { Bh = g_Wt_hi + (size_t)by * 16384; Bl = g_Wt_lo + (size_t)by * 16384; coff = by * 128; }
    if (MODE == 1) { Bh = g_Wot_hi; Bl = g_Wot_lo; }
    if (MODE == 2) { Bh = g_w1t_hi + (size_t)by * 128 * 128; Bl = g_w1t_lo + (size_t)by * 128 * 128; coff = by * 128; }
    if (MODE == 3) { Bh = g_w2t_hi; Bl = g_w2t_lo; }
    float* outbase = (MODE == 0) ? g_Wh : (MODE == 1) ? g_t : (MODE == 2) ? g_u : outp;

    __nv_bfloat16* Ah_s = (__nv_bfloat16*)(sm + OFF_AH);
    __nv_bfloat16* Al_s = (__nv_bfloat16*)(sm + OFF_AL);
    __nv_bfloat16* Bh_s = (__nv_bfloat16*)(sm + OFF_BH);
    __nv_bfloat16* Bl_s = (__nv_bfloat16*)(sm + OFF_BL);
    float* s_v0 = (float*)(sm + 64);
    float* s_v1 = (float*)(sm + 576);
    float* s_v2 = (float*)(sm + 1088);
    float* sst  = (float*)(sm + OFF_AH);    // fp32 staging, reuses tile space

    if (tid < 128) {
        if (MODE == 0) { s_v0[tid] = p0[by * 128 + tid]; s_v1[tid] = p1[by * 128 + tid]; }
        if (MODE == 1) { s_v0[tid] = p1[tid]; s_v1[tid] = p2[tid]; }
        if (MODE == 2) { s_v0[tid] = p0[by * 128 + tid]; }
        if (MODE == 3) { s_v0[tid] = p0[tid]; s_v1[tid] = p1[tid]; s_v2[tid] = p2[tid]; }
    }

    float d[4][4][4];
#pragma unroll
    for (int mi = 0; mi < 4; mi++)
#pragma unroll
        for (int ni = 0; ni < 4; ni++)
#pragma unroll
            for (int j = 0; j < 4; j++) d[mi][ni][j] = 0.f;

    for (int kp = 0; kp < KP; kp++) {
        const int kb0 = kp * 128;
        // A tile: fp32 -> bf16 hi/lo, padded row-major
#pragma unroll
        for (int t = 0; t < 16; t++) {
            int f4 = t * 256 + tid;
            int row = f4 >> 5, q = f4 & 31;
            float4 v = *(const float4*)(A + (size_t)(n0 + row) * LDA + kb0 + q * 4);
            uint2 hi, lo; split4(v, hi, lo);
            size_t off = ((size_t)row * APITCH + q * 4) * 2;
            *(uint2*)((char*)Ah_s + off) = hi;
            *(uint2*)((char*)Al_s + off) = lo;
        }
        // B tile: pre-split bf16 [n][k]
#pragma unroll
        for (int t = 0; t < 8; t++) {
            int f8 = t * 256 + tid;
            int n = f8 >> 4, g = f8 & 15;
            uint4 vh = *(const uint4*)(Bh + (size_t)n * LDB + kb0 + g * 8);
            uint4 vl = *(const uint4*)(Bl + (size_t)n * LDB + kb0 + g * 8);
            size_t off = ((size_t)n * APITCH + g * 8) * 2;
            *(uint4*)((char*)Bh_s + off) = vh;
            *(uint4*)((char*)Bl_s + off) = vl;
        }
        __syncthreads();

#pragma unroll
        for (int ks = 0; ks < 8; ks++) {
            const int ck = ks * 16;
            uint32_t ah[4][4], al[4][4], bh2[4][2], bl2[4][2];
#pragma unroll
            for (int mi = 0; mi < 4; mi++) {
                int r0 = wm + mi * 16 + rr;
                int c0 = ck + cc;
                ah[mi][0] = lds32(Ah_s, r0, c0);     ah[mi][1] = lds32(Ah_s, r0 + 8, c0);
                ah[mi][2] = lds32(Ah_s, r0, c0 + 8); ah[mi][3] = lds32(Ah_s, r0 + 8, c0 + 8);
                al[mi][0] = lds32(Al_s, r0, c0);     al[mi][1] = lds32(Al_s, r0 + 8, c0);
                al[mi][2] = lds32(Al_s, r0, c0 + 8); al[mi][3] = lds32(Al_s, r0 + 8, c0 + 8);
            }
#pragma unroll
            for (int ni = 0; ni < 4; ni++) {
                int nb = wn + ni * 8 + rr;
                int k0 = ck + cc;
                bh2[ni][0] = lds32(Bh_s, nb, k0); bh2[ni][1] = lds32(Bh_s, nb, k0 + 8);
                bl2[ni][0] = lds32(Bl_s, nb, k0); bl2[ni][1] = lds32(Bl_s, nb, k0 + 8);
            }
#pragma unroll
            for (int mi = 0; mi < 4; mi++)
#pragma unroll
                for (int ni = 0; ni < 4; ni++) {
                    mma16816(d[mi][ni], ah[mi], bh2[ni][0], bh2[ni][1]);
                    mma16816(d[mi][ni], ah[mi], bl2[ni][0], bl2[ni][1]);
                    mma16816(d[mi][ni], al[mi], bh2[ni][0], bh2[ni][1]);
                }
        }
        __syncthreads();   // all warps done reading tiles before next overwrite
    }

    // stage D -> smem (pitch SPITCH)
#pragma unroll
    for (int mi = 0; mi < 4; mi++)
#pragma unroll
        for (int ni = 0; ni < 4; ni++) {
            int r = wm + mi * 16 + rr;
            int c = wn + ni * 8 + cc;
            *(float2*)(sst + (size_t)r * SPITCH + c)       = make_float2(d[mi][ni][0], d[mi][ni][1]);
            *(float2*)(sst + (size_t)(r + 8) * SPITCH + c) = make_float2(d[mi][ni][2], d[mi][ni][3]);
        }
    __syncthreads();

    // per-row epilogue (thread per row)
    if (tid < 128) {
        float4* row4 = (float4*)(sst + (size_t)tid * SPITCH);
        const int grow = n0 + tid;
        if (MODE == 0) {
            float ps = 0.f, pd = 0.f;
            const float4* sv0 = (const float4*)s_v0;
            const float4* sv1 = (const float4*)s_v1;
#pragma unroll
            for (int q = 0; q < 32; q++) {
                float4 v = row4[q], a = sv0[q], b = sv1[q];
                ps += v.x * a.x + v.y * a.y + v.z * a.z + v.w * a.w;
                pd += v.x * b.x + v.y * b.y + v.z * b.z + v.w * b.w;
            }
            g_ssrc[(size_t)grow * HH + by] = ps;
            g_sdst[(size_t)grow * HH + by] = pd;
        } else if (MODE == 2) {
            const float4* bv = (const float4*)s_v0;
#pragma unroll
            for (int q = 0; q < 32; q++) {
                float4 v = row4[q], b = bv[q];
                v.x = fmaxf(v.x + b.x, 0.f); v.y = fmaxf(v.y + b.y, 0.f);
                v.z = fmaxf(v.z + b.z, 0.f); v.w = fmaxf(v.w + b.w, 0.f);
                row4[q] = v;
            }
        } else {
            const float4* res = (const float4*)((MODE == 1) ? (p0 + (size_t)grow * 128)
                                                            : (g_t + (size_t)grow * 128));
            const float4* bias = (const float4*)s_v0;   // MODE 3 only
            float sum = 0.f, sq = 0.f;
#pragma unroll
            for (int q = 0; q < 32; q++) {
                float4 v = row4[q], r = res[q];
                v.x += r.x; v.y += r.y; v.z += r.z; v.w += r.w;
                if (MODE == 3) {
                    float4 b = bias[q];
                    v.x += b.x; v.y += b.y; v.z += b.z; v.w += b.w;
                }
                row4[q] = v;
                sum += v.x + v.y + v.z + v.w;
                sq = fmaf(v.x, v.x, fmaf(v.y, v.y, fmaf(v.z, v.z, fmaf(v.w, v.w, sq))));
            }
            const float mu = sum * (1.f / 128.f);
            const float var = sq * (1.f / 128.f) - mu * mu;
            const float rs = rsqrtf(var + 1e-5f);
            const float4* gg = (const float4*)((MODE == 1) ? s_v0 : s_v1);
            const float4* bb = (const float4*)((MODE == 1) ? s_v1 : s_v2);
#pragma unroll
            for (int q = 0; q < 32; q++) {
                float4 v = row4[q], g = gg[q], b = bb[q];
                v.x = (v.x - mu) * rs * g.x + b.x;
                v.y = (v.y - mu) * rs * g.y + b.y;
                v.z = (v.z - mu) * rs * g.z + b.z;
                v.w = (v.w - mu) * rs * g.w + b.w;
                row4[q] = v;
            }
        }
    }
    __syncthreads();

    // coalesced writeback
    for (int idx = tid; idx < 128 * 32; idx += 256) {
        int rr2 = idx >> 5, q = idx & 31;
        float4 v = *(const float4*)(sst + (size_t)rr2 * SPITCH + q * 4);
        *(float4*)(outbase + (size_t)(n0 + rr2) * LDOUT + coff + q * 4) = v;
    }
}

// ---------------- K2: attention softmax + neighbor aggregation ----------------
__global__ void __launch_bounds__(256) k2_attn(
    const int* __restrict__ adj, const int* __restrict__ nlist)
{
    const int node = blockIdx.x;
    const int b = node >> 9;
    const int tx = threadIdx.x;

    __shared__ int   nls[MNB];
    __shared__ int   adjs[MNB];
    __shared__ float es[MNB][HH];
    __shared__ float attn_s[MNB][HH];

    if (tx < MNB) {
        nls[tx]  = nlist[(size_t)node * MNB + tx];
        adjs[tx] = adj[(size_t)node * MNB + tx];
    }
    __syncthreads();

    if (tx < MNB * HH) {
        const int m = tx >> 3, hh = tx & 7;
        float v = g_ssrc[(size_t)node * HH + hh]
                + g_sdst[(size_t)((b << 9) + nls[m]) * HH + hh];
        v = v > 0.f ? v : 0.2f * v;
        if (adjs[m] <= 0) v = -1e9f;
        es[m][hh] = v;
    }
    __syncthreads();

    if (tx < HH) {
        float mx = -3.4e38f;
#pragma unroll
        for (int m = 0; m < MNB; m++) mx = fmaxf(mx, es[m][tx]);
        float ex[MNB], s = 0.f;
#pragma unroll
        for (int m = 0; m < MNB; m++) { ex[m] = expf(es[m][tx] - mx); s += ex[m]; }
        const float inv = 1.f / s;
#pragma unroll
        for (int m = 0; m < MNB; m++) attn_s[m][tx] = ex[m] * inv;
    }
    __syncthreads();

    const int hh = tx >> 5;
    const float4* whb = (const float4*)g_Wh + (size_t)(b << 9) * 256;
    float4 acc = make_float4(0.f, 0.f, 0.f, 0.f);
#pragma unroll
    for (int m = 0; m < MNB; m++) {
        const float wgt = attn_s[m][hh];
        const float4 v = whb[(size_t)nls[m] * 256 + tx];
        acc.x = fmaf(wgt, v.x, acc.x);
        acc.y = fmaf(wgt, v.y, acc.y);
        acc.z = fmaf(wgt, v.z, acc.z);
        acc.w = fmaf(wgt, v.w, acc.w);
    }
    ((float4*)g_agg)[(size_t)node * 256 + tx] = acc;
}

// ---------------------------------------------------------------------------
extern "C" void kernel_launch(void* const* d_in, const int* in_sizes, int n_in,
                              void* d_out, int out_size)
{
    const float* h     = (const float*)d_in[0];
    const int*   adj   = (const int*)d_in[1];
    const int*   nlist = (const int*)d_in[2];
    const float* W     = (const float*)d_in[3];
    const float* a_src = (const float*)d_in[4];
    const float* a_dst = (const float*)d_in[5];
    const float* Wo    = (const float*)d_in[6];
    const float* ln1g  = (const float*)d_in[7];
    const float* ln1b  = (const float*)d_in[8];
    const float* w1    = (const float*)d_in[9];
    const float* b1    = (const float*)d_in[10];
    const float* w2    = (const float*)d_in[11];
    const float* b2    = (const float*)d_in[12];
    const float* ln2g  = (const float*)d_in[13];
    const float* ln2b  = (const float*)d_in[14];
    float* out = (float*)d_out;

    static bool attr_done = false;
    if (!attr_done) {
        cudaFuncSetAttribute(gemm_mma<0>, cudaFuncAttributeMaxDynamicSharedMemorySize, GEMM_SMEM);
        cudaFuncSetAttribute(gemm_mma<1>, cudaFuncAttributeMaxDynamicSharedMemorySize, GEMM_SMEM);
        cudaFuncSetAttribute(gemm_mma<2>, cudaFuncAttributeMaxDynamicSharedMemorySize, GEMM_SMEM);
        cudaFuncSetAttribute(gemm_mma<3>, cudaFuncAttributeMaxDynamicSharedMemorySize, GEMM_SMEM);
        attr_done = true;
    }

    prep_weights<<<1280, 256>>>(W, Wo, w1, w2);
    gemm_mma<0><<<dim3(64, 8), 256, GEMM_SMEM>>>(h, a_src, a_dst, nullptr, nullptr);
    k2_attn<<<BN, 256>>>(adj, nlist);
    gemm_mma<1><<<dim3(64, 1), 256, GEMM_SMEM>>>(nullptr, h, ln1g, ln1b, nullptr);
    gemm_mma<2><<<dim3(64, 2), 256, GEMM_SMEM>>>(nullptr, b1, nullptr, nullptr, nullptr);
    gemm_mma<3><<<dim3(64, 1), 256, GEMM_SMEM>>>(nullptr, b2, ln2g, ln2b, out);
}